// round 4
// baseline (speedup 1.0000x reference)
#include <cuda_runtime.h>
#include <math.h>

#define NCLS 100
#define O 9
#define FH 64
#define LBLOCKS 256     // logits-role blocks: 8 rows each (2048 rows)
#define PBLOCKS 32      // policy-role blocks: 8 warps * 4 pairs (1024 pairs)
#define PPW 4
#define NBLOCKS (LBLOCKS + PBLOCKS)

// counts: [0..127] cnt1[m][v] (even rows), [128..255] cnt2[m][v] (odd rows)
__device__ int   g_cnt[256];        // statically zero; final block re-zeros each launch
__device__ int   g_ticket;          // statically zero; final block resets
__device__ float g_part_pol[72 * PBLOCKS];   // slot-major moment partials
__device__ float g_ab[1024 * 16];   // per pair p: a_k at [p*16+k-1], b_k at [p*16+8+k-1], k=1..8
__device__ float g_part_ce[LBLOCKS];
__device__ float g_part_kl[LBLOCKS];

__device__ __forceinline__ float wredsum(float v) {
#pragma unroll
    for (int o = 16; o; o >>= 1) v += __shfl_xor_sync(0xffffffffu, v, o);
    return v;
}
__device__ __forceinline__ double dredsum(double v) {
#pragma unroll
    for (int o = 16; o; o >>= 1) v += __shfl_xor_sync(0xffffffffu, v, o);
    return v;
}

__global__ __launch_bounds__(256, 2) void fused_kernel(
        const float* __restrict__ slog, const float* __restrict__ tlog,
        const float* __restrict__ spol, const float* __restrict__ tpol,
        const float* __restrict__ W1,   const float* __restrict__ bias1,
        const float* __restrict__ W2,   const float* __restrict__ bias2,
        const int* __restrict__ targets, float* __restrict__ out) {
    // role-specific shared
    __shared__ float sce[8], skl[8];
    __shared__ float w1s[O * 128], w2s[O * 128];
    __shared__ float acc[72];
    // final-phase shared
    __shared__ float red[72], eqs[8], ccs[8];
    __shared__ float s_ce, s_kl;
    __shared__ int   sh_cnt[256];
    __shared__ bool  amLast;

    int tid = threadIdx.x, warp = tid >> 5, lane = tid & 31;
    int bid = blockIdx.x;

    if (bid < LBLOCKS) {
        // ───────── logits role: one warp per row ─────────
        int row = bid * 8 + warp;
        const float* s = slog + row * NCLS;
        const float* t = tlog + row * NCLS;

        if (lane < 8) {
            int v = targets[row * 8 + lane];
            v = v < 0 ? 0 : (v > 15 ? 15 : v);
            atomicAdd(&g_cnt[(row & 1) * 128 + lane * 16 + v], 1);
        }

        float s0 = s[lane], s1 = s[lane + 32], s2 = s[lane + 64];
        float t0 = t[lane], t1 = t[lane + 32], t2 = t[lane + 64];
        bool v3 = lane < (NCLS - 96);
        float s3 = v3 ? s[lane + 96] : -1e30f;
        float t3 = v3 ? t[lane + 96] : -1e30f;

        float ms = fmaxf(fmaxf(s0, s1), fmaxf(s2, s3));
        float mt = fmaxf(fmaxf(t0, t1), fmaxf(t2, t3));
#pragma unroll
        for (int o = 16; o; o >>= 1) {
            ms = fmaxf(ms, __shfl_xor_sync(0xffffffffu, ms, o));
            mt = fmaxf(mt, __shfl_xor_sync(0xffffffffu, mt, o));
        }
        float ms4 = 0.25f * ms, mt4 = 0.25f * mt;

        float es = __expf(s0 - ms) + __expf(s1 - ms) + __expf(s2 - ms)
                 + (v3 ? __expf(s3 - ms) : 0.f);

        float x0 = 0.25f*s0 - ms4, x1 = 0.25f*s1 - ms4, x2 = 0.25f*s2 - ms4, x3 = 0.25f*s3 - ms4;
        float y0 = 0.25f*t0 - mt4, y1 = 0.25f*t1 - mt4, y2 = 0.25f*t2 - mt4, y3 = 0.25f*t3 - mt4;
        float es4 = __expf(x0) + __expf(x1) + __expf(x2) + (v3 ? __expf(x3) : 0.f);
        float e0 = __expf(y0), e1 = __expf(y1), e2 = __expf(y2), e3 = v3 ? __expf(y3) : 0.f;
        float Zt  = e0 + e1 + e2 + e3;
        float sum1 = e0*(y0-x0) + e1*(y1-x1) + e2*(y2-x2) + e3*(y3-x3);

#pragma unroll
        for (int o = 16; o; o >>= 1) {
            es   += __shfl_xor_sync(0xffffffffu, es,   o);
            es4  += __shfl_xor_sync(0xffffffffu, es4,  o);
            Zt   += __shfl_xor_sync(0xffffffffu, Zt,   o);
            sum1 += __shfl_xor_sync(0xffffffffu, sum1, o);
        }
        float lse = __logf(es), lse4 = __logf(es4), lZt = __logf(Zt);

        int lbl = targets[row * 8];                        // 0..9, lives in s0 chunk
        float slbl = __shfl_sync(0xffffffffu, s0, lbl);
        float ce_r = ms + lse - slbl;
        float klr  = sum1 / Zt - lZt + lse4;

        if (lane == 0) { sce[warp] = ce_r; skl[warp] = klr; }
        __syncthreads();
        if (tid == 0) {
            float a = 0.f, b = 0.f;
#pragma unroll
            for (int i = 0; i < 8; i++) { a += sce[i]; b += skl[i]; }
            g_part_ce[bid] = a;
            g_part_kl[bid] = b;
        }
    } else {
        // ───────── policy role: one warp per 4 pairs ─────────
        for (int i = tid; i < O * 128; i += 256) { w1s[i] = W1[i]; w2s[i] = W2[i]; }
        if (tid < 72) acc[tid] = 0.f;
        __syncthreads();

        int b = bid - LBLOCKS;
        int p0 = (b * 8 + warp) * PPW;

        float mom[O];
#pragma unroll
        for (int k = 0; k < O; k++) mom[k] = 0.f;

#pragma unroll
        for (int pi = 0; pi < PPW; pi++) {
            int p = p0 + pi;
            const float* se = spol + (2 * p) * FH;
            const float* so = se + FH;
            const float* te = tpol + (2 * p) * FH;
            const float* to = te + FH;
            float se0 = se[lane], se1 = se[lane + 32];
            float so0 = so[lane], so1 = so[lane + 32];
            float te0 = te[lane], te1 = te[lane + 32];
            float to0 = to[lane], to1 = to[lane + 32];

            float myra = 0.f, myrb = 0.f;
#pragma unroll
            for (int k = 0; k < O; k++) {
                const float* w2k = w2s + k * 128;
                const float* w1k = w1s + k * 128;
                float pa = se0 * w2k[lane] + se1 * w2k[lane + 32];
                float pb = so0 * w2k[lane + 64] + so1 * w2k[lane + 96];
                float pe = te0 * w1k[lane] + te1 * w1k[lane + 32];
                float pd = to0 * w1k[lane + 64] + to1 * w1k[lane + 96];
#pragma unroll
                for (int off = 16; off; off >>= 1) {
                    pa += __shfl_xor_sync(0xffffffffu, pa, off);
                    pb += __shfl_xor_sync(0xffffffffu, pb, off);
                    pe += __shfl_xor_sync(0xffffffffu, pe, off);
                    pd += __shfl_xor_sync(0xffffffffu, pd, off);
                }
                float dv;
                switch (lane) {
                    case 0: dv = pa; break;
                    case 1: dv = pb; break;
                    case 2: dv = pe; break;
                    case 3: dv = pd; break;
                    case 4: dv = (pa - pe) * (pa - pe); break;
                    case 5: dv = (pb - pd) * (pb - pd); break;
                    case 6: dv = pa * pa; break;
                    case 7: dv = pb * pb; break;
                    default: dv = 0.f; break;
                }
                mom[k] += dv;
                if (lane == k - 1) { myra = pa; myrb = pb; }
            }
            if (lane < 8) {
                g_ab[p * 16 + lane]     = myra;   // a_{k=lane+1}
                g_ab[p * 16 + 8 + lane] = myrb;   // b_{k=lane+1}
            }
        }

        if (lane < 8) {
#pragma unroll
            for (int k = 0; k < O; k++) atomicAdd(&acc[k * 8 + lane], mom[k]);
        }
        __syncthreads();
        if (tid < 72) g_part_pol[tid * PBLOCKS + b] = acc[tid];
    }

    // ───────── last-block-done final reduction ─────────
    __threadfence();
    __syncthreads();
    if (tid == 0) {
        int t = atomicAdd(&g_ticket, 1);
        amLast = (t == NBLOCKS - 1);
    }
    __syncthreads();
    if (!amLast) return;

    // phase A: slot reduce + ce/kl reduce + copy counts
    sh_cnt[tid] = g_cnt[tid];
    if (tid < 72) {
        const float4* v = (const float4*)(g_part_pol + tid * PBLOCKS);
        float4 a0 = v[0], a1 = v[1], a2 = v[2], a3 = v[3];
        float4 a4 = v[4], a5 = v[5], a6 = v[6], a7 = v[7];
        red[tid] = ((a0.x+a0.y)+(a0.z+a0.w)) + ((a1.x+a1.y)+(a1.z+a1.w))
                 + ((a2.x+a2.y)+(a2.z+a2.w)) + ((a3.x+a3.y)+(a3.z+a3.w))
                 + ((a4.x+a4.y)+(a4.z+a4.w)) + ((a5.x+a5.y)+(a5.z+a5.w))
                 + ((a6.x+a6.y)+(a6.z+a6.w)) + ((a7.x+a7.y)+(a7.z+a7.w));
    }
    if (warp == 3) {
        float a = 0.f;
        for (int i = lane; i < LBLOCKS; i += 32) a += g_part_ce[i];
        a = wredsum(a);
        if (lane == 0) s_ce = a;
    }
    if (warp == 4) {
        float a = 0.f;
        for (int i = lane; i < LBLOCKS; i += 32) a += g_part_kl[i];
        a = wredsum(a);
        if (lane == 0) s_kl = a;
    }
    __syncthreads();

    if (warp == 5 && lane < 8) {
        int cc = 0;
#pragma unroll
        for (int v = 0; v < 16; v++) cc += sh_cnt[lane * 16 + v] * sh_cnt[128 + lane * 16 + v];
        ccs[lane] = (float)cc;
    }

    // phase B: eq-dot terms, warp m handles component m (t column m, output k=m+1)
    {
        int m = warp;
        float e = 0.f;
        const int* c2 = sh_cnt + 128 + m * 16;
        const int* c1 = sh_cnt + m * 16;
#pragma unroll 4
        for (int j = lane; j < 1024; j += 32) {
            float a = g_ab[j * 16 + m];
            float bb = g_ab[j * 16 + 8 + m];
            int v1 = targets[16 * j + m];     v1 = v1 < 0 ? 0 : (v1 > 15 ? 15 : v1);
            int v2 = targets[16 * j + 8 + m]; v2 = v2 < 0 ? 0 : (v2 > 15 ? 15 : v2);
            e += a * (float)c2[v1] + bb * (float)c1[v2];
        }
        e = wredsum(e);
        if (lane == 0) eqs[m] = e;
    }
    __syncthreads();

    // phase C: closed form, lane-parallel fp64
    if (warp == 0) {
        const double n = 1024.0, n2 = n * n;
        double P = 0.0;
        int k = lane;
        if (k < O) {
            double sa = red[k*8+0], sb = red[k*8+1];
            double sE = red[k*8+2], sd = red[k*8+3];
            double syy = red[k*8+4], sxx = red[k*8+5];
            double saa = red[k*8+6], sbb = red[k*8+7];
            double c = bias2[k], f = bias1[k];
            double dx = sb - sd, dy = sa - sE, dl = c - f;
            double ss = n*sxx + n*syy + n2*dl*dl + 2.0*dx*dy + 2.0*n*dl*(dx + dy);
            double w = (k == 0) ? 1.0 : (k == 1) ? 0.5 : (0.001 / 7.0);
            P = w * ss / n2;
            if (k == 0) {
                P += -(sa + sb + n * c) / n2;                 // kldiv(sI,gI)
            } else {
                int m = k - 1;
                double eq = (double)eqs[m] + c * (double)ccs[m];
                if (k == 1) {
                    P += -0.5 * eq / n2;                      // kldiv(sC,gC)·mean-w
                } else {
                    double sumsq_s = n*sbb + n*saa + n2*c*c + 2.0*sa*sb + 2.0*n*c*(sa + sb);
                    double sum_s = n*(sa + sb) + n2*c;
                    double ssg = 2.0 * eq - sum_s;            // Σ s·g, g = 2·eq−1
                    P += 0.001 * (sumsq_s - 2.0*ssg + n2) / (7.0 * n2);
                }
            }
        }
        double pol = dredsum(P);
        if (lane == 0) {
            double ce = (double)s_ce / 2048.0;
            double kl = (double)s_kl * 16.0 / (2048.0 * 100.0);
            out[0] = (float)(ce + kl + pol);
        }
    }

    // reset persistent state for next launch (deterministic across replays)
    __syncthreads();
    g_cnt[tid] = 0;
    if (tid == 0) g_ticket = 0;
}

extern "C" void kernel_launch(void* const* d_in, const int* in_sizes, int n_in,
                              void* d_out, int out_size) {
    const float* slog = (const float*)d_in[0];
    const float* tlog = (const float*)d_in[1];
    const float* spol = (const float*)d_in[2];
    const float* tpol = (const float*)d_in[3];
    const float* W1   = (const float*)d_in[4];
    const float* b1   = (const float*)d_in[5];
    const float* W2   = (const float*)d_in[6];
    const float* b2   = (const float*)d_in[7];
    const int* targets = (const int*)d_in[8];

    fused_kernel<<<NBLOCKS, 256>>>(slog, tlog, spol, tpol, W1, b1, W2, b2,
                                   targets, (float*)d_out);
}